// round 1
// baseline (speedup 1.0000x reference)
#include <cuda_runtime.h>
#include <cuda_bf16.h>
#include <math.h>

// ---------------- problem constants ----------------
#define BATCH    4
#define SEQ      1024
#define TOK      (BATCH*SEQ)      // 4096 tokens
#define DIM      1024
#define NHEAD    16
#define HDIM     64
#define EXP_OUT  7168             // 3*DIM + 4*DIM
#define MLPD     4096
#define HCAT     5120             // DIM + MLPD
#define COUT     2048             // 2*DIM
#define BHEADS   (BATCH*NHEAD)    // 64

// ---------------- scratch (static device globals; no allocation) ----------------
__device__ float g_xn[(size_t)TOK*DIM];
__device__ float g_ib[EXP_OUT];
__device__ int   g_de[TOK];
__device__ float g_y [(size_t)TOK*EXP_OUT];          // 117 MB
__device__ float g_q [(size_t)BHEADS*SEQ*HDIM];      // (b,h,n,d)
__device__ float g_k [(size_t)BHEADS*SEQ*HDIM];      // (b,h,n,d)
__device__ float g_vt[(size_t)BHEADS*HDIM*SEQ];      // (b,h,d,n)
__device__ float g_ao[(size_t)BHEADS*SEQ*HDIM];      // attn out (b,h,n,d)
__device__ float g_h [(size_t)TOK*HCAT];             // concat(attn, gelu(mlp))
__device__ float g_s [(size_t)BHEADS*SEQ*SEQ];       // 256 MB scores
__device__ float g_o2[(size_t)TOK*COUT];

// ---------------- reduction helpers ----------------
__device__ __forceinline__ float warp_sum(float v){
    #pragma unroll
    for (int o=16;o;o>>=1) v += __shfl_xor_sync(0xffffffffu, v, o);
    return v;
}
__device__ __forceinline__ float warp_max(float v){
    #pragma unroll
    for (int o=16;o;o>>=1) v = fmaxf(v, __shfl_xor_sync(0xffffffffu, v, o));
    return v;
}
__device__ float block_sum(float v, float* sh){
    int lane = threadIdx.x & 31, w = threadIdx.x >> 5;
    v = warp_sum(v);
    if (lane==0) sh[w] = v;
    __syncthreads();
    float r = (lane < ((int)blockDim.x >> 5)) ? sh[lane] : 0.f;
    r = warp_sum(r);
    __syncthreads();
    return r;
}
__device__ float block_max(float v, float* sh){
    int lane = threadIdx.x & 31, w = threadIdx.x >> 5;
    v = warp_max(v);
    if (lane==0) sh[w] = v;
    __syncthreads();
    float r = (lane < ((int)blockDim.x >> 5)) ? sh[lane] : -INFINITY;
    r = warp_max(r);
    __syncthreads();
    return r;
}
__device__ __forceinline__ float gelu_exact(float v){
    return 0.5f * v * (1.f + erff(v * 0.70710678118654752440f));
}

// ---------------- kernels ----------------

// input_bias[e] = mlp_bias[e] for e < 4096 else 0
__global__ void prep_ib_kernel(const float* __restrict__ mlb, float* __restrict__ ib){
    int i = blockIdx.x*blockDim.x + threadIdx.x;
    if (i < EXP_OUT) ib[i] = (i < MLPD) ? mlb[i] : 0.f;
}

// LN1 + fmask -> xn; also d_e per token
__global__ void ln1_kernel(const float* __restrict__ x, const int* __restrict__ emask,
                           const float* __restrict__ g, const float* __restrict__ b,
                           float* __restrict__ xn, int* __restrict__ de_out){
    __shared__ float sh[32];
    int t = blockIdx.x;
    const float* xr = x + (size_t)t*DIM;
    float s1=0.f, s2=0.f;
    for (int i=threadIdx.x;i<DIM;i+=blockDim.x){ float v=xr[i]; s1+=v; s2+=v*v; }
    s1 = block_sum(s1, sh);
    s2 = block_sum(s2, sh);
    float mean = s1 * (1.f/DIM);
    float var  = s2 * (1.f/DIM) - mean*mean;
    float inv  = rsqrtf(var + 1e-5f);
    int de = DIM >> (3 - emask[t]);
    if (threadIdx.x==0) de_out[t] = de;
    float* xo = xn + (size_t)t*DIM;
    for (int i=threadIdx.x;i<DIM;i+=blockDim.x){
        float v = (xr[i]-mean)*inv*g[i] + b[i];
        xo[i] = (i < de) ? v : 0.f;
    }
}

// Generic tiled SGEMM: C[M,N] = scale * (A[M,K] @ B[N,K]^T) + bias[N], batched on z.
template<int BM,int BN,int BK,int TM,int TN>
__global__ void __launch_bounds__((BM/TM)*(BN/TN))
gemm_abt(const float* __restrict__ A, const float* __restrict__ B,
         const float* __restrict__ bias, float* __restrict__ C,
         int M, int N, int K, float scale,
         size_t sA, size_t sB, size_t sC)
{
    constexpr int THREADS = (BM/TM)*(BN/TN);
    constexpr int KV = BK/4;
    constexpr int A_LOADS = BM*KV/THREADS;
    constexpr int B_LOADS = BN*KV/THREADS;
    __shared__ float As[BK][BM+4];
    __shared__ float Bs[BK][BN+4];
    A += (size_t)blockIdx.z * sA;
    B += (size_t)blockIdx.z * sB;
    C += (size_t)blockIdx.z * sC;
    const int tid = threadIdx.x;
    const int m0 = blockIdx.y * BM;
    const int n0 = blockIdx.x * BN;
    const int tx = tid % (BN/TN);
    const int ty = tid / (BN/TN);
    float acc[TM][TN];
    #pragma unroll
    for (int i=0;i<TM;i++)
        #pragma unroll
        for (int j=0;j<TN;j++) acc[i][j]=0.f;

    for (int kt=0; kt<K; kt+=BK){
        #pragma unroll
        for (int i=0;i<A_LOADS;i++){
            int idx = tid + i*THREADS;
            int r = idx / KV, c = idx % KV;
            float4 v = *(const float4*)(A + (size_t)(m0+r)*K + kt + c*4);
            As[c*4+0][r]=v.x; As[c*4+1][r]=v.y; As[c*4+2][r]=v.z; As[c*4+3][r]=v.w;
        }
        #pragma unroll
        for (int i=0;i<B_LOADS;i++){
            int idx = tid + i*THREADS;
            int r = idx / KV, c = idx % KV;
            float4 v = *(const float4*)(B + (size_t)(n0+r)*K + kt + c*4);
            Bs[c*4+0][r]=v.x; Bs[c*4+1][r]=v.y; Bs[c*4+2][r]=v.z; Bs[c*4+3][r]=v.w;
        }
        __syncthreads();
        #pragma unroll
        for (int kk=0;kk<BK;kk++){
            float a[TM], bfr[TN];
            #pragma unroll
            for (int i=0;i<TM;i++) a[i] = As[kk][ty*TM+i];
            #pragma unroll
            for (int j=0;j<TN;j++) bfr[j] = Bs[kk][tx*TN+j];
            #pragma unroll
            for (int i=0;i<TM;i++)
                #pragma unroll
                for (int j=0;j<TN;j++)
                    acc[i][j] += a[i]*bfr[j];
        }
        __syncthreads();
    }
    #pragma unroll
    for (int i=0;i<TM;i++){
        int m = m0 + ty*TM + i;
        #pragma unroll
        for (int j=0;j<TN;j++){
            int n = n0 + tx*TN + j;
            float v = acc[i][j]*scale;
            if (bias) v += bias[n];
            C[(size_t)m*N + n] = v;
        }
    }
}

// From y: q copy, LN2(k), LN2(v)->vt, gelu(mlp)->h tail. One block per token.
__global__ void qkv_kernel(const float* __restrict__ y, const float* __restrict__ mlb,
                           const float* __restrict__ n2g, const float* __restrict__ n2b,
                           float* __restrict__ q, float* __restrict__ k,
                           float* __restrict__ vt, float* __restrict__ h)
{
    __shared__ float sh[32];
    int t = blockIdx.x;
    int b = t / SEQ, n = t % SEQ;
    const float* yr = y + (size_t)t*EXP_OUT;

    // q copy
    for (int i=threadIdx.x;i<DIM;i+=blockDim.x){
        int hh = i >> 6, d = i & 63;
        q[(((size_t)b*NHEAD + hh)*SEQ + n)*HDIM + d] = yr[i];
    }
    // LN2(k)
    {
        float s1=0.f,s2=0.f;
        for (int i=threadIdx.x;i<DIM;i+=blockDim.x){ float v=yr[DIM+i]; s1+=v; s2+=v*v; }
        s1 = block_sum(s1, sh); s2 = block_sum(s2, sh);
        float mean=s1*(1.f/DIM), inv=rsqrtf(s2*(1.f/DIM)-mean*mean+1e-5f);
        for (int i=threadIdx.x;i<DIM;i+=blockDim.x){
            float v = (yr[DIM+i]-mean)*inv*n2g[i] + n2b[i];
            int hh = i >> 6, d = i & 63;
            k[(((size_t)b*NHEAD + hh)*SEQ + n)*HDIM + d] = v;
        }
    }
    // LN2(v) -> transposed per head (d major)
    {
        float s1=0.f,s2=0.f;
        for (int i=threadIdx.x;i<DIM;i+=blockDim.x){ float v=yr[2*DIM+i]; s1+=v; s2+=v*v; }
        s1 = block_sum(s1, sh); s2 = block_sum(s2, sh);
        float mean=s1*(1.f/DIM), inv=rsqrtf(s2*(1.f/DIM)-mean*mean+1e-5f);
        for (int i=threadIdx.x;i<DIM;i+=blockDim.x){
            float v = (yr[2*DIM+i]-mean)*inv*n2g[i] + n2b[i];
            int hh = i >> 6, d = i & 63;
            vt[(((size_t)b*NHEAD + hh)*HDIM + d)*SEQ + n] = v;
        }
    }
    // gelu(mlp_hidden): y already carries input_bias; reference adds mlp_bias again
    for (int j=threadIdx.x;j<MLPD;j+=blockDim.x){
        float v = yr[3*DIM + j] + mlb[j];
        h[(size_t)t*HCAT + DIM + j] = gelu_exact(v);
    }
}

// softmax over rows of 1024 (65536 rows)
__global__ void softmax_kernel(float* __restrict__ s){
    __shared__ float sh[32];
    float* row = s + (size_t)blockIdx.x * SEQ;
    float mx = -INFINITY;
    for (int i=threadIdx.x;i<SEQ;i+=blockDim.x) mx = fmaxf(mx, row[i]);
    mx = block_max(mx, sh);
    float sum = 0.f;
    for (int i=threadIdx.x;i<SEQ;i+=blockDim.x){
        float e = __expf(row[i]-mx);
        row[i] = e; sum += e;
    }
    sum = block_sum(sum, sh);
    float inv = 1.f/sum;
    for (int i=threadIdx.x;i<SEQ;i+=blockDim.x) row[i] *= inv;
}

// (b,h,n,d) -> h[t, h*64+d]
__global__ void copy_ao_kernel(const float* __restrict__ ao, float* __restrict__ h){
    size_t idx = (size_t)blockIdx.x*blockDim.x + threadIdx.x;  // TOK*DIM
    int d  = idx & 63;
    int n  = (idx >> 6) & (SEQ-1);
    int hh = (idx >> 16) & (NHEAD-1);
    int b  = idx >> 20;
    float v = ao[idx];
    h[((size_t)(b*SEQ + n))*HCAT + hh*HDIM + d] = v;
}

// final combine
__global__ void epilogue_kernel(const float* __restrict__ x, const float* __restrict__ probs,
                                const float* __restrict__ alpha, const int* __restrict__ de,
                                const float* __restrict__ o2, float* __restrict__ out){
    size_t idx = (size_t)blockIdx.x*blockDim.x + threadIdx.x;  // TOK*DIM
    int t = (int)(idx >> 10);
    int e = (int)(idx & (DIM-1));
    float fm = (e < de[t]) ? 1.f : 0.f;
    float a = o2[(size_t)t*COUT + e] * fm;
    float m = o2[(size_t)t*COUT + DIM + e] * fm;
    out[idx] = a + x[idx] + (alpha[0]*probs[t] + 1.f) * m;
}

// ---------------- launcher ----------------
extern "C" void kernel_launch(void* const* d_in, const int* in_sizes, int n_in,
                              void* d_out, int out_size)
{
    const float* x    = (const float*)d_in[0];
    const int*   em   = (const int*)  d_in[1];
    const float* pr   = (const float*)d_in[2];
    const float* We   = (const float*)d_in[3];
    const float* mlb  = (const float*)d_in[4];
    const float* Wc   = (const float*)d_in[5];
    const float* cb   = (const float*)d_in[6];
    const float* n1g  = (const float*)d_in[7];
    const float* n1b  = (const float*)d_in[8];
    const float* n2g  = (const float*)d_in[9];
    const float* n2b  = (const float*)d_in[10];
    const float* alp  = (const float*)d_in[11];
    float* out = (float*)d_out;

    float *xn,*ib,*y,*q,*k,*vt,*ao,*h,*s,*o2; int* de;
    cudaGetSymbolAddress((void**)&xn, g_xn);
    cudaGetSymbolAddress((void**)&ib, g_ib);
    cudaGetSymbolAddress((void**)&de, g_de);
    cudaGetSymbolAddress((void**)&y , g_y );
    cudaGetSymbolAddress((void**)&q , g_q );
    cudaGetSymbolAddress((void**)&k , g_k );
    cudaGetSymbolAddress((void**)&vt, g_vt);
    cudaGetSymbolAddress((void**)&ao, g_ao);
    cudaGetSymbolAddress((void**)&h , g_h );
    cudaGetSymbolAddress((void**)&s , g_s );
    cudaGetSymbolAddress((void**)&o2, g_o2);

    // 1. input bias
    prep_ib_kernel<<<(EXP_OUT+255)/256, 256>>>(mlb, ib);
    // 2. LN1 + mask
    ln1_kernel<<<TOK, 256>>>(x, em, n1g, n1b, xn, de);
    // 3. expand GEMM: y = xn @ We^T + ib   (4096 x 7168 x 1024)
    gemm_abt<128,128,16,8,8><<<dim3(EXP_OUT/128, TOK/128, 1), 256>>>(
        xn, We, ib, y, TOK, EXP_OUT, DIM, 1.f, 0, 0, 0);
    // 4. q/k/v/mlp split
    qkv_kernel<<<TOK, 256>>>(y, mlb, n2g, n2b, q, k, vt, h);
    // 5. scores = (q*scale) @ k^T   (64 batches of 1024x1024x64)
    gemm_abt<128,128,16,8,8><<<dim3(SEQ/128, SEQ/128, BHEADS), 256>>>(
        q, k, nullptr, s, SEQ, SEQ, HDIM, 0.125f,
        (size_t)SEQ*HDIM, (size_t)SEQ*HDIM, (size_t)SEQ*SEQ);
    // 6. softmax
    softmax_kernel<<<BHEADS*SEQ, 128>>>(s);
    // 7. attn_out = P @ V   (64 batches of 1024x64x1024; B = vt [64,1024])
    gemm_abt<128,64,16,8,4><<<dim3(HDIM/64, SEQ/128, BHEADS), 256>>>(
        s, vt, nullptr, ao, SEQ, HDIM, SEQ, 1.f,
        (size_t)SEQ*SEQ, (size_t)HDIM*SEQ, (size_t)SEQ*HDIM);
    // 8. scatter attn_out into h head
    copy_ao_kernel<<<(TOK*DIM)/256, 256>>>(ao, h);
    // 9. contract GEMM: o2 = h @ Wc^T + cb  (4096 x 2048 x 5120)
    gemm_abt<128,128,16,8,8><<<dim3(COUT/128, TOK/128, 1), 256>>>(
        h, Wc, cb, o2, TOK, COUT, HCAT, 1.f, 0, 0, 0);
    // 10. epilogue
    epilogue_kernel<<<(TOK*DIM)/256, 256>>>(x, pr, alp, de, o2, out);
}

// round 5
// speedup vs baseline: 2.0280x; 2.0280x over previous
#include <cuda_runtime.h>
#include <cuda_bf16.h>
#include <math.h>

// ---------------- problem constants ----------------
#define BATCH    4
#define SEQ      1024
#define TOK      (BATCH*SEQ)      // 4096 tokens
#define DIM      1024
#define NHEAD    16
#define HDIM     64
#define EXP_OUT  7168             // 3*DIM + 4*DIM
#define MLPD     4096
#define HCAT     5120             // DIM + MLPD
#define COUT     2048             // 2*DIM
#define BHEADS   (BATCH*NHEAD)    // 64

// ---------------- scratch (static device globals; no allocation) ----------------
__device__ float g_xn[(size_t)TOK*DIM];
__device__ float g_ib[EXP_OUT];
__device__ int   g_de[TOK];
__device__ float g_y [(size_t)TOK*EXP_OUT];          // 117 MB
__device__ float g_q [(size_t)BHEADS*SEQ*HDIM];      // (b,h,n,d)
__device__ float g_k [(size_t)BHEADS*SEQ*HDIM];      // (b,h,n,d)
__device__ float g_vt[(size_t)BHEADS*HDIM*SEQ];      // (b,h,d,n)
__device__ float g_h [(size_t)TOK*HCAT];             // concat(attn, gelu(mlp))
__device__ float g_s [(size_t)BHEADS*SEQ*SEQ];       // 256 MB scores
__device__ float g_o2[(size_t)TOK*COUT];

// ---------------- helpers ----------------
__device__ __forceinline__ float warp_sum(float v){
    #pragma unroll
    for (int o=16;o;o>>=1) v += __shfl_xor_sync(0xffffffffu, v, o);
    return v;
}
__device__ __forceinline__ float warp_max(float v){
    #pragma unroll
    for (int o=16;o;o>>=1) v = fmaxf(v, __shfl_xor_sync(0xffffffffu, v, o));
    return v;
}
__device__ float block_sum(float v, float* sh){
    int lane = threadIdx.x & 31, w = threadIdx.x >> 5;
    v = warp_sum(v);
    if (lane==0) sh[w] = v;
    __syncthreads();
    float r = (lane < ((int)blockDim.x >> 5)) ? sh[lane] : 0.f;
    r = warp_sum(r);
    __syncthreads();
    return r;
}
__device__ float block_max(float v, float* sh){
    int lane = threadIdx.x & 31, w = threadIdx.x >> 5;
    v = warp_max(v);
    if (lane==0) sh[w] = v;
    __syncthreads();
    float r = (lane < ((int)blockDim.x >> 5)) ? sh[lane] : -INFINITY;
    r = warp_max(r);
    __syncthreads();
    return r;
}
__device__ __forceinline__ float gelu_exact(float v){
    return 0.5f * v * (1.f + erff(v * 0.70710678118654752440f));
}
// round fp32 -> tf32 (rna), keep in a float register (bit pattern)
__device__ __forceinline__ float tf32r(float x){
    unsigned u;
    asm("cvt.rna.tf32.f32 %0, %1;" : "=r"(u) : "f"(x));
    return __uint_as_float(u);
}
__device__ __forceinline__ void mma_tf32(float* c, const unsigned* a, const unsigned* b){
    asm volatile("mma.sync.aligned.m16n8k8.row.col.f32.tf32.tf32.f32 "
        "{%0,%1,%2,%3},{%4,%5,%6,%7},{%8,%9},{%0,%1,%2,%3};"
        : "+f"(c[0]),"+f"(c[1]),"+f"(c[2]),"+f"(c[3])
        : "r"(a[0]),"r"(a[1]),"r"(a[2]),"r"(a[3]),"r"(b[0]),"r"(b[1]));
}

// ---------------- kernels ----------------

__global__ void prep_ib_kernel(const float* __restrict__ mlb, float* __restrict__ ib){
    int i = blockIdx.x*blockDim.x + threadIdx.x;
    if (i < EXP_OUT) ib[i] = (i < MLPD) ? mlb[i] : 0.f;
}

__global__ void ln1_kernel(const float* __restrict__ x, const int* __restrict__ emask,
                           const float* __restrict__ g, const float* __restrict__ b,
                           float* __restrict__ xn, int* __restrict__ de_out){
    __shared__ float sh[32];
    int t = blockIdx.x;
    const float* xr = x + (size_t)t*DIM;
    float s1=0.f, s2=0.f;
    for (int i=threadIdx.x;i<DIM;i+=blockDim.x){ float v=xr[i]; s1+=v; s2+=v*v; }
    s1 = block_sum(s1, sh);
    s2 = block_sum(s2, sh);
    float mean = s1 * (1.f/DIM);
    float var  = s2 * (1.f/DIM) - mean*mean;
    float inv  = rsqrtf(var + 1e-5f);
    int de = DIM >> (3 - emask[t]);
    if (threadIdx.x==0) de_out[t] = de;
    float* xo = xn + (size_t)t*DIM;
    for (int i=threadIdx.x;i<DIM;i+=blockDim.x){
        float v = (xr[i]-mean)*inv*g[i] + b[i];
        xo[i] = (i < de) ? v : 0.f;
    }
}

// ---------------- tf32 tensor-core GEMM ----------------
// C[M,N] = scale * (A[M,K] @ B[N,K]^T) + bias[N], batched on z.
// Output addressing generalized: Cbase = C + (z>>4)*sCo + (z&15)*sCi,
// element (row,col) at Cbase + row*ldc + col. For plain batching use
// sCi = stride, sCo = 16*stride, ldc = N.
template<int BM,int BN,int WARPS_M,int WARPS_N>
__global__ void __launch_bounds__(WARPS_M*WARPS_N*32)
gemm_tf32(const float* __restrict__ A, const float* __restrict__ B,
          const float* __restrict__ bias, float* __restrict__ C,
          int M, int N, int K, float scale,
          size_t sA, size_t sB, size_t sCo, size_t sCi, int ldc)
{
    constexpr int BK = 16;
    constexpr int THREADS = WARPS_M*WARPS_N*32;
    constexpr int WM = BM/WARPS_M;
    constexpr int WN = BN/WARPS_N;
    constexpr int MT = WM/16;
    constexpr int NT = WN/8;
    constexpr int LA = BM*(BK/4)/THREADS;   // float4 loads per thread for A
    constexpr int LB = BN*(BK/4)/THREADS;   // float4 loads per thread for B

    __shared__ float As[2][BK][BM+4];
    __shared__ float Bs[2][BK][BN+4];

    A += (size_t)blockIdx.z * sA;
    B += (size_t)blockIdx.z * sB;
    C += (size_t)(blockIdx.z >> 4) * sCo + (size_t)(blockIdx.z & 15) * sCi;

    const int tid  = threadIdx.x;
    const int lane = tid & 31;
    const int warp = tid >> 5;
    const int g    = lane >> 2;   // group id 0..7
    const int t4   = lane & 3;    // thread in group 0..3
    const int wm0  = (warp / WARPS_N) * WM;
    const int wn0  = (warp % WARPS_N) * WN;
    const int m0   = blockIdx.y * BM;
    const int n0   = blockIdx.x * BN;

    float acc[MT][NT][4];
    #pragma unroll
    for (int i=0;i<MT;i++)
        #pragma unroll
        for (int j=0;j<NT;j++)
            #pragma unroll
            for (int r=0;r<4;r++) acc[i][j][r]=0.f;

    const int nk = K / BK;

    // ---- prologue: load tile 0 directly into smem buf 0 ----
    {
        #pragma unroll
        for (int l=0;l<LA;l++){
            int slot = tid + l*THREADS;
            int row = slot >> 2, c4 = slot & 3;
            float4 v = *(const float4*)(A + (size_t)(m0+row)*K + c4*4);
            As[0][c4*4+0][row]=tf32r(v.x); As[0][c4*4+1][row]=tf32r(v.y);
            As[0][c4*4+2][row]=tf32r(v.z); As[0][c4*4+3][row]=tf32r(v.w);
        }
        #pragma unroll
        for (int l=0;l<LB;l++){
            int slot = tid + l*THREADS;
            int row = slot >> 2, c4 = slot & 3;
            float4 v = *(const float4*)(B + (size_t)(n0+row)*K + c4*4);
            Bs[0][c4*4+0][row]=tf32r(v.x); Bs[0][c4*4+1][row]=tf32r(v.y);
            Bs[0][c4*4+2][row]=tf32r(v.z); Bs[0][c4*4+3][row]=tf32r(v.w);
        }
    }
    __syncthreads();

    for (int kt=0; kt<nk; kt++){
        const int buf = kt & 1;
        // prefetch next tile into registers (overlap with mma)
        float4 pa[LA], pb[LB];
        if (kt+1 < nk){
            int koff = (kt+1)*BK;
            #pragma unroll
            for (int l=0;l<LA;l++){
                int slot = tid + l*THREADS;
                int row = slot >> 2, c4 = slot & 3;
                pa[l] = *(const float4*)(A + (size_t)(m0+row)*K + koff + c4*4);
            }
            #pragma unroll
            for (int l=0;l<LB;l++){
                int slot = tid + l*THREADS;
                int row = slot >> 2, c4 = slot & 3;
                pb[l] = *(const float4*)(B + (size_t)(n0+row)*K + koff + c4*4);
            }
        }
        // compute on current buffer: two k8 sub-steps
        #pragma unroll
        for (int s=0;s<BK;s+=8){
            unsigned af[MT][4], bf[NT][2];
            #pragma unroll
            for (int mt=0;mt<MT;mt++){
                int r = wm0 + mt*16;
                af[mt][0] = __float_as_uint(As[buf][s+t4  ][r+g  ]);
                af[mt][1] = __float_as_uint(As[buf][s+t4  ][r+g+8]);
                af[mt][2] = __float_as_uint(As[buf][s+t4+4][r+g  ]);
                af[mt][3] = __float_as_uint(As[buf][s+t4+4][r+g+8]);
            }
            #pragma unroll
            for (int nt=0;nt<NT;nt++){
                int c = wn0 + nt*8;
                bf[nt][0] = __float_as_uint(Bs[buf][s+t4  ][c+g]);
                bf[nt][1] = __float_as_uint(Bs[buf][s+t4+4][c+g]);
            }
            #pragma unroll
            for (int mt=0;mt<MT;mt++)
                #pragma unroll
                for (int nt=0;nt<NT;nt++)
                    mma_tf32(acc[mt][nt], af[mt], bf[nt]);
        }
        // store prefetched tile into other buffer
        if (kt+1 < nk){
            int nb = buf ^ 1;
            #pragma unroll
            for (int l=0;l<LA;l++){
                int slot = tid + l*THREADS;
                int row = slot >> 2, c4 = slot & 3;
                As[nb][c4*4+0][row]=tf32r(pa[l].x); As[nb][c4*4+1][row]=tf32r(pa[l].y);
                As[nb][c4*4+2][row]=tf32r(pa[l].z); As[nb][c4*4+3][row]=tf32r(pa[l].w);
            }
            #pragma unroll
            for (int l=0;l<LB;l++){
                int slot = tid + l*THREADS;
                int row = slot >> 2, c4 = slot & 3;
                Bs[nb][c4*4+0][row]=tf32r(pb[l].x); Bs[nb][c4*4+1][row]=tf32r(pb[l].y);
                Bs[nb][c4*4+2][row]=tf32r(pb[l].z); Bs[nb][c4*4+3][row]=tf32r(pb[l].w);
            }
            __syncthreads();
        }
    }

    // ---- epilogue ----
    #pragma unroll
    for (int mt=0;mt<MT;mt++){
        #pragma unroll
        for (int nt=0;nt<NT;nt++){
            int row = m0 + wm0 + mt*16 + g;
            int col = n0 + wn0 + nt*8 + t4*2;
            float b0 = bias ? bias[col]   : 0.f;
            float b1 = bias ? bias[col+1] : 0.f;
            float2 v0 = make_float2(acc[mt][nt][0]*scale + b0, acc[mt][nt][1]*scale + b1);
            float2 v1 = make_float2(acc[mt][nt][2]*scale + b0, acc[mt][nt][3]*scale + b1);
            *(float2*)(C + (size_t)row*ldc + col)     = v0;
            *(float2*)(C + (size_t)(row+8)*ldc + col) = v1;
        }
    }
}

// From y: q copy, LN2(k), LN2(v)->vt, gelu(mlp)->h tail. One block per token.
__global__ void qkv_kernel(const float* __restrict__ y, const float* __restrict__ mlb,
                           const float* __restrict__ n2g, const float* __restrict__ n2b,
                           float* __restrict__ q, float* __restrict__ k,
                           float* __restrict__ vt, float* __restrict__ h)
{
    __shared__ float sh[32];
    int t = blockIdx.x;
    int b = t / SEQ, n = t % SEQ;
    const float* yr = y + (size_t)t*EXP_OUT;

    for (int i=threadIdx.x;i<DIM;i+=blockDim.x){
        int hh = i >> 6, d = i & 63;
        q[(((size_t)b*NHEAD + hh)*SEQ + n)*HDIM + d] = yr[i];
    }
    {
        float s1=0.f,s2=0.f;
        for (int i=threadIdx.x;i<DIM;i+=blockDim.x){ float v=yr[DIM+i]; s1+=v; s2+=v*v; }
        s1 = block_sum(s1, sh); s2 = block_sum(s2, sh);
        float mean=s1*(1.f/DIM), inv=rsqrtf(s2*(1.f/DIM)-mean*mean+1e-5f);
        for (int i=threadIdx.x;i<DIM;i+=blockDim.x){
            float v = (yr[DIM+i]-mean)*inv*n2g[i] + n2b[i];
            int hh = i >> 6, d = i & 63;
            k[(((size_t)b*NHEAD + hh)*SEQ + n)*HDIM + d] = v;
        }
    }
    {
        float s1=0.f,s2=0.f;
        for (int i=threadIdx.x;i<DIM;i+=blockDim.x){ float v=yr[2*DIM+i]; s1+=v; s2+=v*v; }
        s1 = block_sum(s1, sh); s2 = block_sum(s2, sh);
        float mean=s1*(1.f/DIM), inv=rsqrtf(s2*(1.f/DIM)-mean*mean+1e-5f);
        for (int i=threadIdx.x;i<DIM;i+=blockDim.x){
            float v = (yr[2*DIM+i]-mean)*inv*n2g[i] + n2b[i];
            int hh = i >> 6, d = i & 63;
            vt[(((size_t)b*NHEAD + hh)*HDIM + d)*SEQ + n] = v;
        }
    }
    for (int j=threadIdx.x;j<MLPD;j+=blockDim.x){
        float v = yr[3*DIM + j] + mlb[j];
        h[(size_t)t*HCAT + DIM + j] = gelu_exact(v);
    }
}

__global__ void softmax_kernel(float* __restrict__ s){
    __shared__ float sh[32];
    float* row = s + (size_t)blockIdx.x * SEQ;
    float mx = -INFINITY;
    for (int i=threadIdx.x;i<SEQ;i+=blockDim.x) mx = fmaxf(mx, row[i]);
    mx = block_max(mx, sh);
    float sum = 0.f;
    for (int i=threadIdx.x;i<SEQ;i+=blockDim.x){
        float e = __expf(row[i]-mx);
        row[i] = e; sum += e;
    }
    sum = block_sum(sum, sh);
    float inv = 1.f/sum;
    for (int i=threadIdx.x;i<SEQ;i+=blockDim.x) row[i] *= inv;
}

__global__ void epilogue_kernel(const float* __restrict__ x, const float* __restrict__ probs,
                                const float* __restrict__ alpha, const int* __restrict__ de,
                                const float* __restrict__ o2, float* __restrict__ out){
    size_t idx = (size_t)blockIdx.x*blockDim.x + threadIdx.x;  // TOK*DIM
    int t = (int)(idx >> 10);
    int e = (int)(idx & (DIM-1));
    float fm = (e < de[t]) ? 1.f : 0.f;
    float a = o2[(size_t)t*COUT + e] * fm;
    float m = o2[(size_t)t*COUT + DIM + e] * fm;
    out[idx] = a + x[idx] + (alpha[0]*probs[t] + 1.f) * m;
}

// ---------------- launcher ----------------
extern "C" void kernel_launch(void* const* d_in, const int* in_sizes, int n_in,
                              void* d_out, int out_size)
{
    const float* x    = (const float*)d_in[0];
    const int*   em   = (const int*)  d_in[1];
    const float* pr   = (const float*)d_in[2];
    const float* We   = (const float*)d_in[3];
    const float* mlb  = (const float*)d_in[4];
    const float* Wc   = (const float*)d_in[5];
    const float* cb   = (const float*)d_in[6];
    const float* n1g  = (const float*)d_in[7];
    const float* n1b  = (const float*)d_in[8];
    const float* n2g  = (const float*)d_in[9];
    const float* n2b  = (const float*)d_in[10];
    const float* alp  = (const float*)d_in[11];
    float* out = (float*)d_out;

    float *xn,*ib,*y,*q,*k,*vt,*h,*s,*o2; int* de;
    cudaGetSymbolAddress((void**)&xn, g_xn);
    cudaGetSymbolAddress((void**)&ib, g_ib);
    cudaGetSymbolAddress((void**)&de, g_de);
    cudaGetSymbolAddress((void**)&y , g_y );
    cudaGetSymbolAddress((void**)&q , g_q );
    cudaGetSymbolAddress((void**)&k , g_k );
    cudaGetSymbolAddress((void**)&vt, g_vt);
    cudaGetSymbolAddress((void**)&h , g_h );
    cudaGetSymbolAddress((void**)&s , g_s );
    cudaGetSymbolAddress((void**)&o2, g_o2);

    // 1. input bias
    prep_ib_kernel<<<(EXP_OUT+255)/256, 256>>>(mlb, ib);
    // 2. LN1 + mask
    ln1_kernel<<<TOK, 256>>>(x, em, n1g, n1b, xn, de);
    // 3. expand GEMM: y = xn @ We^T + ib   (4096 x 7168 x 1024)
    gemm_tf32<128,128,2,4><<<dim3(EXP_OUT/128, TOK/128, 1), 256>>>(
        xn, We, ib, y, TOK, EXP_OUT, DIM, 1.f, 0, 0, 0, 0, EXP_OUT);
    // 4. q/k/v/mlp split
    qkv_kernel<<<TOK, 256>>>(y, mlb, n2g, n2b, q, k, vt, h);
    // 5. scores = (q @ k^T) * scale   (64 batches of 1024x1024x64)
    gemm_tf32<128,128,2,4><<<dim3(SEQ/128, SEQ/128, BHEADS), 256>>>(
        q, k, nullptr, s, SEQ, SEQ, HDIM, 0.125f,
        (size_t)SEQ*HDIM, (size_t)SEQ*HDIM,
        (size_t)16*SEQ*SEQ, (size_t)SEQ*SEQ, SEQ);
    // 6. softmax
    softmax_kernel<<<BHEADS*SEQ, 128>>>(s);
    // 7. attn_out = P @ V, written DIRECTLY into h[t, hh*64+d]
    //    z = b*16+hh: Cbase = h + b*(1024*5120) + hh*64, ldc = 5120
    gemm_tf32<128,64,4,2><<<dim3(HDIM/64, SEQ/128, BHEADS), 256>>>(
        s, vt, nullptr, h, SEQ, HDIM, SEQ, 1.f,
        (size_t)SEQ*SEQ, (size_t)HDIM*SEQ,
        (size_t)SEQ*HCAT, (size_t)HDIM, HCAT);
    // 8. contract GEMM: o2 = h @ Wc^T + cb  (4096 x 2048 x 5120)
    gemm_tf32<128,128,2,4><<<dim3(COUT/128, TOK/128, 1), 256>>>(
        h, Wc, cb, o2, TOK, COUT, HCAT, 1.f, 0, 0, 0, 0, COUT);
    // 9. epilogue
    epilogue_kernel<<<(TOK*DIM)/256, 256>>>(x, pr, alp, de, o2, out);
}

// round 16
// speedup vs baseline: 3.1072x; 1.5322x over previous
#include <cuda_runtime.h>
#include <math.h>

// ---------------- problem constants ----------------
#define BATCH    4
#define SEQ      1024
#define TOK      (BATCH*SEQ)      // 4096 tokens
#define DIM      1024
#define NHEAD    16
#define HDIM     64
#define EXP_OUT  7168             // 3*DIM + 4*DIM
#define MLPD     4096
#define HCAT     5120             // DIM + MLPD
#define COUT     2048             // 2*DIM
#define BHEADS   (BATCH*NHEAD)    // 64

// ---------------- scratch (static device globals; no allocation) ----------------
__device__ float g_xn[(size_t)TOK*DIM];
__device__ float g_ib[EXP_OUT];
__device__ int   g_de[TOK];
__device__ float g_y [(size_t)TOK*EXP_OUT];
__device__ float g_q [(size_t)BHEADS*SEQ*HDIM];      // (b,h,n,d)  tf32-rounded
__device__ float g_k [(size_t)BHEADS*SEQ*HDIM];      // (b,h,n,d)  tf32-rounded
__device__ float g_vt[(size_t)BHEADS*HDIM*SEQ];      // (b,h,d,n)  tf32-rounded
__device__ float g_h [(size_t)TOK*HCAT];             // concat(attn, gelu(mlp)) tf32-rounded
__device__ float g_s [(size_t)BHEADS*SEQ*SEQ];       // scores / probs
__device__ float g_o2[(size_t)TOK*COUT];
__device__ float g_wet[(size_t)EXP_OUT*DIM];         // tf32-rounded expand weight
__device__ float g_wct[(size_t)COUT*HCAT];           // tf32-rounded contract weight

// ---------------- helpers ----------------
__device__ __forceinline__ float warp_sum(float v){
    #pragma unroll
    for (int o=16;o;o>>=1) v += __shfl_xor_sync(0xffffffffu, v, o);
    return v;
}
__device__ __forceinline__ float warp_max(float v){
    #pragma unroll
    for (int o=16;o;o>>=1) v = fmaxf(v, __shfl_xor_sync(0xffffffffu, v, o));
    return v;
}
__device__ float block_sum(float v, float* sh){
    int lane = threadIdx.x & 31, w = threadIdx.x >> 5;
    v = warp_sum(v);
    if (lane==0) sh[w] = v;
    __syncthreads();
    float r = (lane < ((int)blockDim.x >> 5)) ? sh[lane] : 0.f;
    r = warp_sum(r);
    __syncthreads();
    return r;
}
__device__ float block_max(float v, float* sh){
    int lane = threadIdx.x & 31, w = threadIdx.x >> 5;
    v = warp_max(v);
    if (lane==0) sh[w] = v;
    __syncthreads();
    float r = (lane < ((int)blockDim.x >> 5)) ? sh[lane] : -INFINITY;
    r = warp_max(r);
    __syncthreads();
    return r;
}
__device__ __forceinline__ float gelu_exact(float v){
    return 0.5f * v * (1.f + erff(v * 0.70710678118654752440f));
}
// round fp32 -> tf32 (rna), keep bit pattern in a float
__device__ __forceinline__ float tf32r(float x){
    unsigned u;
    asm("cvt.rna.tf32.f32 %0, %1;" : "=r"(u) : "f"(x));
    return __uint_as_float(u);
}
__device__ __forceinline__ void mma_tf32(float* c, const unsigned* a, const unsigned* b){
    asm volatile("mma.sync.aligned.m16n8k8.row.col.f32.tf32.tf32.f32 "
        "{%0,%1,%2,%3},{%4,%5,%6,%7},{%8,%9},{%0,%1,%2,%3};"
        : "+f"(c[0]),"+f"(c[1]),"+f"(c[2]),"+f"(c[3])
        : "r"(a[0]),"r"(a[1]),"r"(a[2]),"r"(a[3]),"r"(b[0]),"r"(b[1]));
}
__device__ __forceinline__ void cp_async16(void* dst_smem, const void* src){
    unsigned d = (unsigned)__cvta_generic_to_shared(dst_smem);
    asm volatile("cp.async.cg.shared.global [%0], [%1], 16;\n" :: "r"(d), "l"(src));
}
__device__ __forceinline__ void cp_commit(){
    asm volatile("cp.async.commit_group;\n" ::: "memory");
}
__device__ __forceinline__ void cp_wait1(){
    asm volatile("cp.async.wait_group 1;\n" ::: "memory");
}

// ---------------- small kernels ----------------

__global__ void prep_ib_kernel(const float* __restrict__ mlb, float* __restrict__ ib){
    int i = blockIdx.x*blockDim.x + threadIdx.x;
    if (i < EXP_OUT) ib[i] = (i < MLPD) ? mlb[i] : 0.f;
}

// round both weight matrices to tf32 bit patterns (float4 vectorized)
__global__ void prep_w_kernel(const float* __restrict__ we, const float* __restrict__ wc,
                              float* __restrict__ wet, float* __restrict__ wct){
    const size_t NE = (size_t)EXP_OUT*DIM/4;   // float4 count
    const size_t NC = (size_t)COUT*HCAT/4;
    size_t i = (size_t)blockIdx.x*blockDim.x + threadIdx.x;
    if (i < NE){
        float4 v = ((const float4*)we)[i];
        v.x=tf32r(v.x); v.y=tf32r(v.y); v.z=tf32r(v.z); v.w=tf32r(v.w);
        ((float4*)wet)[i] = v;
    } else if (i < NE + NC){
        size_t j = i - NE;
        float4 v = ((const float4*)wc)[j];
        v.x=tf32r(v.x); v.y=tf32r(v.y); v.z=tf32r(v.z); v.w=tf32r(v.w);
        ((float4*)wct)[j] = v;
    }
}

__global__ void ln1_kernel(const float* __restrict__ x, const int* __restrict__ emask,
                           const float* __restrict__ g, const float* __restrict__ b,
                           float* __restrict__ xn, int* __restrict__ de_out){
    __shared__ float sh[32];
    int t = blockIdx.x;
    const float* xr = x + (size_t)t*DIM;
    float s1=0.f, s2=0.f;
    for (int i=threadIdx.x;i<DIM;i+=blockDim.x){ float v=xr[i]; s1+=v; s2+=v*v; }
    s1 = block_sum(s1, sh);
    s2 = block_sum(s2, sh);
    float mean = s1 * (1.f/DIM);
    float var  = s2 * (1.f/DIM) - mean*mean;
    float inv  = rsqrtf(var + 1e-5f);
    int de = DIM >> (3 - emask[t]);
    if (threadIdx.x==0) de_out[t] = de;
    float* xo = xn + (size_t)t*DIM;
    for (int i=threadIdx.x;i<DIM;i+=blockDim.x){
        float v = (xr[i]-mean)*inv*g[i] + b[i];
        xo[i] = (i < de) ? tf32r(v) : 0.f;
    }
}

// ---------------- tf32 tensor-core GEMM, cp.async 3-stage, BK=32 ----------------
// C[M,N] = scale * (A[M,K] @ B[N,K]^T) + bias[N], batched on z.
// A and B must contain tf32-rounded bit patterns already.
// Output addressing: Cbase = C + (z>>4)*sCo + (z&15)*sCi, elem at row*ldc+col.
// If round_out != 0, outputs are tf32-rounded on store.
template<int BM,int BN,int WARPS_M,int WARPS_N>
__global__ void __launch_bounds__(WARPS_M*WARPS_N*32, 2)
gemm_tf32_pipe(const float* __restrict__ A, const float* __restrict__ B,
               const float* __restrict__ bias, float* __restrict__ C,
               int M, int N, int K, float scale, int round_out,
               size_t sA, size_t sB, size_t sCo, size_t sCi, int ldc)
{
    constexpr int BK = 32;
    constexpr int STAGES = 3;
    constexpr int LDS_ = 36;                  // smem row stride (floats), conflict-free
    constexpr int THREADS = WARPS_M*WARPS_N*32;
    constexpr int WM = BM/WARPS_M;
    constexpr int WN = BN/WARPS_N;
    constexpr int MT = WM/16;
    constexpr int NT = WN/8;
    constexpr int LA = BM*BK/(THREADS*4);     // 16B chunks per thread for A
    constexpr int LB = BN*BK/(THREADS*4);

    extern __shared__ float sm[];
    float* smA = sm;                              // STAGES * BM * LDS_
    float* smB = sm + (size_t)STAGES*BM*LDS_;     // STAGES * BN * LDS_

    A += (size_t)blockIdx.z * sA;
    B += (size_t)blockIdx.z * sB;
    C += (size_t)(blockIdx.z >> 4) * sCo + (size_t)(blockIdx.z & 15) * sCi;

    const int tid  = threadIdx.x;
    const int lane = tid & 31;
    const int warp = tid >> 5;
    const int g    = lane >> 2;
    const int t4   = lane & 3;
    const int wm0  = (warp / WARPS_N) * WM;
    const int wn0  = (warp % WARPS_N) * WN;
    const int m0   = blockIdx.y * BM;
    const int n0   = blockIdx.x * BN;
    const int nk   = K / BK;

    auto load_tile = [&](int kt, int stg){
        const float* Ag = A + (size_t)m0*K + kt*BK;
        float* As = smA + (size_t)stg*BM*LDS_;
        #pragma unroll
        for (int l=0;l<LA;l++){
            int idx = tid + l*THREADS;          // chunk id, 8 chunks per row
            int row = idx >> 3;
            int col = (idx & 7)*4;
            cp_async16(As + row*LDS_ + col, Ag + (size_t)row*K + col);
        }
        const float* Bg = B + (size_t)n0*K + kt*BK;
        float* Bs = smB + (size_t)stg*BN*LDS_;
        #pragma unroll
        for (int l=0;l<LB;l++){
            int idx = tid + l*THREADS;
            int row = idx >> 3;
            int col = (idx & 7)*4;
            cp_async16(Bs + row*LDS_ + col, Bg + (size_t)row*K + col);
        }
    };

    float acc[MT][NT][4];
    #pragma unroll
    for (int i=0;i<MT;i++)
        #pragma unroll
        for (int j=0;j<NT;j++)
            #pragma unroll
            for (int r=0;r<4;r++) acc[i][j][r]=0.f;

    // prologue: stage 0 and 1 (all our K have nk >= 2)
    load_tile(0, 0); cp_commit();
    load_tile(1, 1); cp_commit();

    for (int kt=0; kt<nk; kt++){
        cp_wait1();
        __syncthreads();
        // issue next tile into stage (kt+2)%3 == (kt-1)%3 (safe: compute kt-1 done by all)
        if (kt+2 < nk) load_tile(kt+2, (kt+2)%STAGES);
        cp_commit();

        const float* As = smA + (size_t)(kt%STAGES)*BM*LDS_;
        const float* Bs = smB + (size_t)(kt%STAGES)*BN*LDS_;
        #pragma unroll
        for (int s=0;s<BK;s+=8){
            unsigned af[MT][4], bf[NT][2];
            #pragma unroll
            for (int mt=0;mt<MT;mt++){
                int r = wm0 + mt*16;
                af[mt][0] = __float_as_uint(As[(r+g  )*LDS_ + s+t4  ]);
                af[mt][1] = __float_as_uint(As[(r+g+8)*LDS_ + s+t4  ]);
                af[mt][2] = __float_as_uint(As[(r+g  )*LDS_ + s+t4+4]);
                af[mt][3] = __float_as_uint(As[(r+g+8)*LDS_ + s+t4+4]);
            }
            #pragma unroll
            for (int nt=0;nt<NT;nt++){
                int c = wn0 + nt*8;
                bf[nt][0] = __float_as_uint(Bs[(c+g)*LDS_ + s+t4  ]);
                bf[nt][1] = __float_as_uint(Bs[(c+g)*LDS_ + s+t4+4]);
            }
            #pragma unroll
            for (int mt=0;mt<MT;mt++)
                #pragma unroll
                for (int nt=0;nt<NT;nt++)
                    mma_tf32(acc[mt][nt], af[mt], bf[nt]);
        }
    }

    // ---- epilogue ----
    #pragma unroll
    for (int mt=0;mt<MT;mt++){
        #pragma unroll
        for (int nt=0;nt<NT;nt++){
            int row = m0 + wm0 + mt*16 + g;
            int col = n0 + wn0 + nt*8 + t4*2;
            float b0 = bias ? bias[col]   : 0.f;
            float b1 = bias ? bias[col+1] : 0.f;
            float o0 = acc[mt][nt][0]*scale + b0;
            float o1 = acc[mt][nt][1]*scale + b1;
            float o2 = acc[mt][nt][2]*scale + b0;
            float o3 = acc[mt][nt][3]*scale + b1;
            if (round_out){ o0=tf32r(o0); o1=tf32r(o1); o2=tf32r(o2); o3=tf32r(o3); }
            *(float2*)(C + (size_t)row*ldc + col)     = make_float2(o0, o1);
            *(float2*)(C + (size_t)(row+8)*ldc + col) = make_float2(o2, o3);
        }
    }
}

// From y: q copy, LN2(k), LN2(v)->vt, gelu(mlp)->h tail. One block per token.
// All GEMM-feeding outputs written tf32-rounded.
__global__ void qkv_kernel(const float* __restrict__ y, const float* __restrict__ mlb,
                           const float* __restrict__ n2g, const float* __restrict__ n2b,
                           float* __restrict__ q, float* __restrict__ k,
                           float* __restrict__ vt, float* __restrict__ h)
{
    __shared__ float sh[32];
    int t = blockIdx.x;
    int b = t / SEQ, n = t % SEQ;
    const float* yr = y + (size_t)t*EXP_OUT;

    for (int i=threadIdx.x;i<DIM;i+=blockDim.x){
        int hh = i >> 6, d = i & 63;
        q[(((size_t)b*NHEAD + hh)*SEQ + n)*HDIM + d] = tf32r(yr[i]);
    }
    {
        float s1=0.f,s2=0.f;
        for (int i=threadIdx.x;i<DIM;i+=blockDim.x){ float v=yr[DIM+i]; s1+=v; s2+=v*v; }
        s1 = block_sum(s1, sh); s2 = block_sum(s2, sh);
        float mean=s1*(1.f/DIM), inv=rsqrtf(s2*(1.f/DIM)-mean*mean+1e-5f);
        for (int i=threadIdx.x;i<DIM;i+=blockDim.x){
            float v = (yr[DIM+i]-mean)*inv*n2g[i] + n2b[i];
            int hh = i >> 6, d = i & 63;
            k[(((size_t)b*NHEAD + hh)*SEQ + n)*HDIM + d] = tf32r(v);
        }
    }
    {
        float s1=0.f,s2=0.f;
        for (int i=threadIdx.x;i<DIM;i+=blockDim.x){ float v=yr[2*DIM+i]; s1+=v; s2+=v*v; }
        s1 = block_sum(s1, sh); s2 = block_sum(s2, sh);
        float mean=s1*(1.f/DIM), inv=rsqrtf(s2*(1.f/DIM)-mean*mean+1e-5f);
        for (int i=threadIdx.x;i<DIM;i+=blockDim.x){
            float v = (yr[2*DIM+i]-mean)*inv*n2g[i] + n2b[i];
            int hh = i >> 6, d = i & 63;
            vt[(((size_t)b*NHEAD + hh)*HDIM + d)*SEQ + n] = tf32r(v);
        }
    }
    for (int j=threadIdx.x;j<MLPD;j+=blockDim.x){
        float v = yr[3*DIM + j] + mlb[j];
        h[(size_t)t*HCAT + DIM + j] = tf32r(gelu_exact(v));
    }
}

// softmax over rows of 1024; output tf32-rounded (feeds PV GEMM)
__global__ void softmax_kernel(float* __restrict__ s){
    __shared__ float sh[32];
    float* row = s + (size_t)blockIdx.x * SEQ;
    float mx = -INFINITY;
    for (int i=threadIdx.x;i<SEQ;i+=blockDim.x) mx = fmaxf(mx, row[i]);
    mx = block_max(mx, sh);
    float sum = 0.f;
    for (int i=threadIdx.x;i<SEQ;i+=blockDim.x){
        float e = __expf(row[i]-mx);
        row[i] = e; sum += e;
    }
    sum = block_sum(sum, sh);
    float inv = 1.f/sum;
    for (int i=threadIdx.x;i<SEQ;i+=blockDim.x) row[i] = tf32r(row[i]*inv);
}

__global__ void epilogue_kernel(const float* __restrict__ x, const float* __restrict__ probs,
                                const float* __restrict__ alpha, const int* __restrict__ de,
                                const float* __restrict__ o2, float* __restrict__ out){
    size_t idx = (size_t)blockIdx.x*blockDim.x + threadIdx.x;  // TOK*DIM
    int t = (int)(idx >> 10);
    int e = (int)(idx & (DIM-1));
    float fm = (e < de[t]) ? 1.f : 0.f;
    float a = o2[(size_t)t*COUT + e] * fm;
    float m = o2[(size_t)t*COUT + DIM + e] * fm;
    out[idx] = a + x[idx] + (alpha[0]*probs[t] + 1.f) * m;
}

// ---------------- launcher ----------------
extern "C" void kernel_launch(void* const* d_in, const int* in_sizes, int n_in,
                              void* d_out, int out_size)
{
    const float* x    = (const float*)d_in[0];
    const int*   em   = (const int*)  d_in[1];
    const float* pr   = (const float*)d_in[2];
    const float* We   = (const float*)d_in[3];
    const float* mlb  = (const float*)d_in[4];
    const float* Wc   = (const float*)d_in[5];
    const float* cb   = (const float*)d_in[6];
    const float* n1g  = (const float*)d_in[7];
    const float* n1b  = (const float*)d_in[8];
    const float* n2g  = (const float*)d_in[9];
    const float* n2b  = (const float*)d_in[10];
    const float* alp  = (const float*)d_in[11];
    float* out = (float*)d_out;

    float *xn,*ib,*y,*q,*k,*vt,*h,*s,*o2,*wet,*wct; int* de;
    cudaGetSymbolAddress((void**)&xn, g_xn);
    cudaGetSymbolAddress((void**)&ib, g_ib);
    cudaGetSymbolAddress((void**)&de, g_de);
    cudaGetSymbolAddress((void**)&y , g_y );
    cudaGetSymbolAddress((void**)&q , g_q );
    cudaGetSymbolAddress((void**)&k , g_k );
    cudaGetSymbolAddress((void**)&vt, g_vt);
    cudaGetSymbolAddress((void**)&h , g_h );
    cudaGetSymbolAddress((void**)&s , g_s );
    cudaGetSymbolAddress((void**)&o2, g_o2);
    cudaGetSymbolAddress((void**)&wet, g_wet);
    cudaGetSymbolAddress((void**)&wct, g_wct);

    // dynamic smem: 3 stages * (BM+BN) * 36 floats
    const int SMEM_BIG = 3*(128+128)*36*4;   // 110592
    const int SMEM_PV  = 3*(128+ 64)*36*4;   //  82944
    cudaFuncSetAttribute(gemm_tf32_pipe<128,128,2,4>,
                         cudaFuncAttributeMaxDynamicSharedMemorySize, SMEM_BIG);
    cudaFuncSetAttribute(gemm_tf32_pipe<128,64,4,2>,
                         cudaFuncAttributeMaxDynamicSharedMemorySize, SMEM_PV);

    // 1. input bias + weight rounding
    prep_ib_kernel<<<(EXP_OUT+255)/256, 256>>>(mlb, ib);
    {
        size_t n4 = ((size_t)EXP_OUT*DIM + (size_t)COUT*HCAT)/4;
        prep_w_kernel<<<(unsigned)((n4+255)/256), 256>>>(We, Wc, wet, wct);
    }
    // 2. LN1 + mask (tf32-rounded output)
    ln1_kernel<<<TOK, 256>>>(x, em, n1g, n1b, xn, de);
    // 3. expand GEMM: y = xn @ We^T + ib   (4096 x 7168 x 1024)
    gemm_tf32_pipe<128,128,2,4><<<dim3(EXP_OUT/128, TOK/128, 1), 256, SMEM_BIG>>>(
        xn, wet, ib, y, TOK, EXP_OUT, DIM, 1.f, 0, 0, 0, 0, 0, EXP_OUT);
    // 4. q/k/v/mlp split (tf32-rounded outputs)
    qkv_kernel<<<TOK, 256>>>(y, mlb, n2g, n2b, q, k, vt, h);
    // 5. scores = (q @ k^T) * scale   (64 batches of 1024x1024x64)
    gemm_tf32_pipe<128,128,2,4><<<dim3(SEQ/128, SEQ/128, BHEADS), 256, SMEM_BIG>>>(
        q, k, nullptr, s, SEQ, SEQ, HDIM, 0.125f, 0,
        (size_t)SEQ*HDIM, (size_t)SEQ*HDIM,
        (size_t)16*SEQ*SEQ, (size_t)SEQ*SEQ, SEQ);
    // 6. softmax (tf32-rounded output)
    softmax_kernel<<<BHEADS*SEQ, 128>>>(s);
    // 7. attn_out = P @ V, written DIRECTLY into h[t, hh*64+d], tf32-rounded
    gemm_tf32_pipe<128,64,4,2><<<dim3(HDIM/64, SEQ/128, BHEADS), 256, SMEM_PV>>>(
        s, vt, nullptr, h, SEQ, HDIM, SEQ, 1.f, 1,
        (size_t)SEQ*SEQ, (size_t)HDIM*SEQ,
        (size_t)SEQ*HCAT, (size_t)HDIM, HCAT);
    // 8. contract GEMM: o2 = h @ Wc^T + cb  (4096 x 2048 x 5120)
    gemm_tf32_pipe<128,128,2,4><<<dim3(COUT/128, TOK/128, 1), 256, SMEM_BIG>>>(
        h, wct, cb, o2, TOK, COUT, HCAT, 1.f, 0, 0, 0, 0, 0, COUT);
    // 9. epilogue
    epilogue_kernel<<<(TOK*DIM)/256, 256>>>(x, pr, alp, de, o2, out);
}